// round 1
// baseline (speedup 1.0000x reference)
#include <cuda_runtime.h>
#include <cstdint>

#define BATCH 16
#define A_N   261888
#define PRE   2000
#define POST  1000
#define NB    4096          // histogram buckets over [0,1)
#define CAP   4096          // candidate capacity per image (sort size, power of 2)
#define NW    32            // 32 x uint64 words cover 2048 >= PRE bits
#define CH    64            // NMS scan chunk rows
#define IMGF      1024.0f
#define NMS_THR_F 0.7f
#define MIN_SZ_F  16.0f

// ---------------- device scratch (static: no allocation allowed) ----------------
__device__ float               g_score[BATCH * A_N];        // masked score, -1 = invalid
__device__ int                 g_hist[BATCH * NB];
__device__ int                 g_thr[BATCH];
__device__ int                 g_cnt[BATCH];
__device__ unsigned long long  g_cand[BATCH * CAP];
__device__ float4              g_box[BATCH * PRE];
__device__ float               g_sc2[BATCH * PRE];
__device__ unsigned long long  g_mask[BATCH * PRE * NW];    // 8.2 MB IoU suppression bits
__device__ unsigned long long  g_keep[BATCH * NW];

// ---------------- decode + clip, matching reference order of ops ----------------
__device__ __forceinline__ float4 decode_clip(const float4 a, const float4 d) {
    float aw = a.z - a.x;
    float ah = a.w - a.y;
    float ax = a.x + 0.5f * aw;
    float ay = a.y + 0.5f * ah;
    float dw = fminf(d.z, 4.0f);
    float dh = fminf(d.w, 4.0f);
    float px = d.x * aw + ax;
    float py = d.y * ah + ay;
    float pw = expf(dw) * aw;
    float ph = expf(dh) * ah;
    float x1 = fminf(fmaxf(px - 0.5f * pw, 0.0f), IMGF);
    float y1 = fminf(fmaxf(py - 0.5f * ph, 0.0f), IMGF);
    float x2 = fminf(fmaxf(px + 0.5f * pw, 0.0f), IMGF);
    float y2 = fminf(fmaxf(py + 0.5f * ph, 0.0f), IMGF);
    return make_float4(x1, y1, x2, y2);
}

// ---------------- kernel 0: zero per-launch state ----------------
__global__ void k_zero() {
    int i = blockIdx.x * blockDim.x + threadIdx.x;
    if (i < BATCH * NB) g_hist[i] = 0;
    if (i < BATCH) g_cnt[i] = 0;
}

// ---------------- kernel 1: decode, mask, histogram ----------------
__global__ void k_decode(const float4* __restrict__ anchors,
                         const float4* __restrict__ deltas,
                         const float* __restrict__ scores) {
    __shared__ int h[NB];
    int b = blockIdx.x >> 6;
    int chunk = blockIdx.x & 63;
    const int per = A_N / 64;          // 4092 exactly
    int start = chunk * per;
    for (int i = threadIdx.x; i < NB; i += blockDim.x) h[i] = 0;
    __syncthreads();
    for (int i = start + threadIdx.x; i < start + per; i += blockDim.x) {
        float4 a = anchors[i];
        float4 d = deltas[(size_t)b * A_N + i];
        float  s = scores[(size_t)b * A_N + i];
        float4 bx = decode_clip(a, d);
        bool valid = (bx.z - bx.x >= MIN_SZ_F) && (bx.w - bx.y >= MIN_SZ_F);
        float ms = valid ? s : -1.0f;
        g_score[(size_t)b * A_N + i] = ms;
        if (valid) {
            int bk = (int)(ms * (float)NB);
            bk = min(max(bk, 0), NB - 1);
            atomicAdd(&h[bk], 1);
        }
    }
    __syncthreads();
    for (int i = threadIdx.x; i < NB; i += blockDim.x)
        if (h[i]) atomicAdd(&g_hist[b * NB + i], h[i]);
}

// ---------------- kernel 2: find threshold bucket (suffix count >= PRE) ----------------
__global__ void k_thr() {
    int b = blockIdx.x;
    __shared__ int csum[128];
    int t = threadIdx.x;
    int s = 0;
    for (int j = 0; j < 32; j++) s += g_hist[b * NB + (NB - 1 - (t * 32 + j))];
    csum[t] = s;
    __syncthreads();
    if (t == 0) {
        int run = 0;
        int thr = 0;
        bool found = false;
        for (int c = 0; c < 128 && !found; c++) {
            if (run + csum[c] >= PRE) {
                for (int j = 0; j < 32; j++) {
                    int bk = NB - 1 - (c * 32 + j);
                    run += g_hist[b * NB + bk];
                    if (run >= PRE) { thr = bk; found = true; break; }
                }
            } else {
                run += csum[c];
            }
        }
        g_thr[b] = found ? thr : 0;
    }
}

// ---------------- kernel 3: collect candidates >= threshold bucket ----------------
__global__ void k_collect() {
    int b = blockIdx.x >> 6;
    int chunk = blockIdx.x & 63;
    const int per = A_N / 64;
    int start = chunk * per;
    int thr = g_thr[b];
    for (int i = start + threadIdx.x; i < start + per; i += blockDim.x) {
        float s = g_score[(size_t)b * A_N + i];
        if (s >= 0.0f) {
            int bk = min((int)(s * (float)NB), NB - 1);
            if (bk >= thr) {
                int pos = atomicAdd(&g_cnt[b], 1);
                if (pos < CAP) {
                    unsigned lo = ~(unsigned)i;   // lower index wins ties
                    g_cand[b * CAP + pos] =
                        ((unsigned long long)__float_as_uint(s) << 32) | lo;
                }
            }
        }
    }
}

// ---------------- kernel 4: bitonic sort (desc) + gather top-PRE boxes ----------------
__global__ void k_sort(const float4* __restrict__ anchors,
                       const float4* __restrict__ deltas) {
    __shared__ unsigned long long sk[CAP];   // 32 KB
    int b = blockIdx.x;
    int C = min(g_cnt[b], CAP);
    for (int i = threadIdx.x; i < CAP; i += blockDim.x)
        sk[i] = (i < C) ? g_cand[b * CAP + i] : 0ull;
    __syncthreads();
    for (int k = 2; k <= CAP; k <<= 1) {
        for (int j = k >> 1; j > 0; j >>= 1) {
            for (int i = threadIdx.x; i < CAP; i += blockDim.x) {
                int ixj = i ^ j;
                if (ixj > i) {
                    bool up = (i & k) == 0;   // up segment -> descending order
                    unsigned long long x = sk[i], y = sk[ixj];
                    bool sw = up ? (x < y) : (x > y);
                    if (sw) { sk[i] = y; sk[ixj] = x; }
                }
            }
            __syncthreads();
        }
    }
    for (int i = threadIdx.x; i < PRE; i += blockDim.x) {
        unsigned long long key = sk[i];
        unsigned idx = ~(unsigned)(key & 0xffffffffu);
        float sc;
        float4 bx;
        if (key != 0ull && idx < A_N) {
            sc = __uint_as_float((unsigned)(key >> 32));
            bx = decode_clip(anchors[idx], deltas[(size_t)b * A_N + idx]);
        } else {
            sc = 0.0f;
            bx = make_float4(0.f, 0.f, 0.f, 0.f);
        }
        g_box[b * PRE + i] = bx;
        g_sc2[b * PRE + i] = sc;
    }
}

// ---------------- kernel 5: IoU suppression bitmask ----------------
__global__ void k_iou() {
    __shared__ float4 cb[64];
    __shared__ float  ca[64];
    int b = blockIdx.z;
    int rowbase = blockIdx.y * 64;
    int colbase = blockIdx.x * 64;
    int t = threadIdx.x;
    int j = colbase + t;
    float4 cj = (j < PRE) ? g_box[b * PRE + j] : make_float4(0.f, 0.f, 0.f, 0.f);
    cb[t] = cj;
    ca[t] = (cj.z - cj.x) * (cj.w - cj.y);
    __syncthreads();
    int i = rowbase + t;
    if (i >= PRE) return;
    float4 bi = g_box[b * PRE + i];
    float  ai = (bi.z - bi.x) * (bi.w - bi.y);
    unsigned long long word = 0ull;
    if (colbase + 63 > i) {
        #pragma unroll 8
        for (int jj = 0; jj < 64; jj++) {
            int jg = colbase + jj;
            if (jg > i && jg < PRE) {
                float4 bb = cb[jj];
                float lx = fmaxf(bi.x, bb.x), ly = fmaxf(bi.y, bb.y);
                float rx = fminf(bi.z, bb.z), ry = fminf(bi.w, bb.w);
                float w = fmaxf(rx - lx, 0.0f), h = fmaxf(ry - ly, 0.0f);
                float inter = w * h;
                float iou = inter / (ai + ca[jj] - inter + 1e-6f);
                if (iou > NMS_THR_F) word |= (1ull << jj);
            }
        }
    }
    g_mask[((size_t)b * PRE + i) * NW + blockIdx.x] = word;
}

// ---------------- kernel 6: serial greedy scan (warp0) + chunk prefetch ----------------
__global__ void k_nms() {
    __shared__ unsigned long long buf[2][CH * NW];   // 32 KB double buffer
    const int NCH = (PRE + CH - 1) / CH;             // 32
    int b = blockIdx.x;
    int tid = threadIdx.x;
    const unsigned long long* mrow = &g_mask[(size_t)b * PRE * NW];
    // preload chunk 0
    {
        int n0 = min(CH, PRE) * NW;
        for (int i = tid; i < n0; i += blockDim.x) buf[0][i] = mrow[i];
    }
    __syncthreads();
    unsigned long long remv = 0ull;   // lane t of warp 0 owns removal word t
    int warp = tid >> 5;
    for (int c = 0; c < NCH; c++) {
        int rows = min(CH, PRE - c * CH);
        if (warp == 0) {
            int t = tid;   // 0..31
            for (int r = 0; r < rows; r++) {
                int i = c * CH + r;
                unsigned long long roww = buf[c & 1][r * NW + t];
                unsigned long long wv = __shfl_sync(0xffffffffu, remv, i >> 6);
                if (((wv >> (i & 63)) & 1ull) == 0ull) remv |= roww;
            }
        } else if (c + 1 < NCH) {
            int rows2 = min(CH, PRE - (c + 1) * CH);
            int n = rows2 * NW;
            int base = (c + 1) * CH * NW;
            for (int i = tid - 32; i < n; i += blockDim.x - 32)
                buf[(c + 1) & 1][i] = mrow[base + i];
        }
        __syncthreads();
    }
    if (tid < 32) {
        unsigned long long keep = ~remv;
        if (tid == NW - 1) keep &= (1ull << (PRE - (NW - 1) * 64)) - 1ull;  // 16 valid bits
        g_keep[b * NW + tid] = keep;
    }
}

// ---------------- kernel 7: compact kept boxes into output ----------------
__global__ void k_out(float* __restrict__ out) {
    __shared__ int pref[NW];
    __shared__ unsigned long long kw[NW];
    int b = blockIdx.x;
    int tid = threadIdx.x;
    for (int i = tid; i < POST * 5; i += blockDim.x) out[(size_t)b * POST * 5 + i] = 0.0f;
    if (tid < NW) kw[tid] = g_keep[b * NW + tid];
    __syncthreads();
    if (tid < 32) {
        int pc = __popcll(kw[tid]);
        int v = pc;
        for (int o = 1; o < 32; o <<= 1) {
            int n = __shfl_up_sync(0xffffffffu, v, o);
            if (tid >= o) v += n;
        }
        pref[tid] = v - pc;   // exclusive prefix of kept counts
    }
    __syncthreads();
    for (int i = tid; i < PRE; i += blockDim.x) {
        int w = i >> 6, bit = i & 63;
        unsigned long long kv = kw[w];
        if ((kv >> bit) & 1ull) {
            int rank = pref[w] + __popcll(kv & ((1ull << bit) - 1ull));
            if (rank < POST) {
                float4 bx = g_box[b * PRE + i];
                float sc = g_sc2[b * PRE + i];
                float* o = &out[((size_t)b * POST + rank) * 5];
                o[0] = bx.x; o[1] = bx.y; o[2] = bx.z; o[3] = bx.w; o[4] = sc;
            }
        }
    }
}

// ---------------- launch ----------------
extern "C" void kernel_launch(void* const* d_in, const int* in_sizes, int n_in,
                              void* d_out, int out_size) {
    const float4* anchors = (const float4*)d_in[0];   // (A,4)
    const float4* deltas  = (const float4*)d_in[1];   // (B,A,4)
    const float*  scores  = (const float*)d_in[2];    // (B,A)
    float* out = (float*)d_out;                        // (B,POST,5)

    k_zero   <<<(BATCH * NB + 255) / 256, 256>>>();
    k_decode <<<BATCH * 64, 512>>>(anchors, deltas, scores);
    k_thr    <<<BATCH, 128>>>();
    k_collect<<<BATCH * 64, 512>>>();
    k_sort   <<<BATCH, 1024>>>(anchors, deltas);
    k_iou    <<<dim3(NW, (PRE + 63) / 64, BATCH), 64>>>();
    k_nms    <<<BATCH, 1024>>>();
    k_out    <<<BATCH, 256>>>(out);
}